// round 2
// baseline (speedup 1.0000x reference)
#include <cuda_runtime.h>
#include <cstdint>

#define NN 8192
#define FF 128
#define NEG 0.2f

// Scratch (no allocations allowed -> __device__ globals)
__device__ float g_xp[(size_t)NN * FF];   // x' = x@W + b  (4 MB, L2-resident)
__device__ float g_ssrc[NN];
__device__ float g_sdst[NN];
__device__ unsigned g_maxbits;            // ordered-encoded max of s_dst

__global__ void k_init() { g_maxbits = 0u; }

// ---------------------------------------------------------------------------
// K1: x' = x @ W + bias      (8192x128 @ 128x128 fp32)
// block = 256 threads, 32 rows per block; W half-tile (64x128) in shared.
// ---------------------------------------------------------------------------
__global__ void k_gemm(const float* __restrict__ x,
                       const float* __restrict__ w,
                       const float* __restrict__ bias) {
    __shared__ float ws[64][128];   // [kk][c]
    __shared__ float xs[32][64];    // [r][kk]
    const int tid = threadIdx.x;
    const int row0 = blockIdx.x * 32;
    const int c  = tid & 127;
    const int rr = tid >> 7;        // 0 or 1 -> rows rr*16 .. rr*16+15

    float acc[16];
#pragma unroll
    for (int q = 0; q < 16; ++q) acc[q] = 0.f;

    for (int kb = 0; kb < 128; kb += 64) {
        for (int t = tid; t < 64 * 128; t += 256)
            ws[t >> 7][t & 127] = w[(kb + (t >> 7)) * 128 + (t & 127)];
        for (int t = tid; t < 32 * 64; t += 256) {
            int r = t >> 6, kk = t & 63;
            xs[r][kk] = x[(size_t)(row0 + r) * 128 + kb + kk];
        }
        __syncthreads();
#pragma unroll 4
        for (int kk = 0; kk < 64; ++kk) {
            float wv = ws[kk][c];
#pragma unroll
            for (int q = 0; q < 16; ++q)
                acc[q] += xs[rr * 16 + q][kk] * wv;   // broadcast LDS
        }
        __syncthreads();
    }
    const float b = bias[c];
#pragma unroll
    for (int q = 0; q < 16; ++q)
        g_xp[(size_t)(row0 + rr * 16 + q) * 128 + c] = acc[q] + b;
}

// ---------------------------------------------------------------------------
// K2: s_src[i] = x'_i . phi[:F],  s_dst[i] = x'_i . phi[F:], global max(s_dst)
// warp per row.
// ---------------------------------------------------------------------------
__global__ void k_score(const float* __restrict__ phi) {
    const int warp = threadIdx.x >> 5, lane = threadIdx.x & 31;
    const int i = blockIdx.x * 8 + warp;
    const float4* xr = (const float4*)(g_xp + (size_t)i * FF);
    const float4* pl = (const float4*)phi;
    const float4* ph = (const float4*)(phi + FF);
    float4 xv = xr[lane], a = pl[lane], b = ph[lane];
    float s1 = xv.x * a.x + xv.y * a.y + xv.z * a.z + xv.w * a.w;
    float s2 = xv.x * b.x + xv.y * b.y + xv.z * b.z + xv.w * b.w;
#pragma unroll
    for (int o = 16; o; o >>= 1) {
        s1 += __shfl_xor_sync(0xffffffffu, s1, o);
        s2 += __shfl_xor_sync(0xffffffffu, s2, o);
    }
    if (lane == 0) {
        g_ssrc[i] = s1;
        g_sdst[i] = s2;
        unsigned bits = __float_as_uint(s2);
        unsigned enc = bits ^ ((bits >> 31) ? 0xFFFFFFFFu : 0x80000000u);
        atomicMax(&g_maxbits, enc);   // order-independent -> deterministic
    }
}

// ---------------------------------------------------------------------------
// K3: fused masked softmax + aggregation, one block (8 warps) per row i.
// Warp w scans j in [w*1024, w*1024+1024): coalesced float4 adj loads,
// ballot-enumerate nonzeros (fixed order -> deterministic), gather x'_j
// from L2 with weight exp(leaky(s_i+s_j) - m_i). Fixed-order warp combine.
// ---------------------------------------------------------------------------
__global__ void k_attn(const float* __restrict__ adj, float* __restrict__ out) {
    const int i = blockIdx.x;
    const int warp = threadIdx.x >> 5, lane = threadIdx.x & 31;

    const unsigned u = g_maxbits;
    const float dmax = __uint_as_float(u ^ ((u >> 31) ? 0x80000000u : 0xFFFFFFFFu));
    const float si = g_ssrc[i];
    float mv = si + dmax; mv = mv > 0.f ? mv : NEG * mv;   // >= all row scores

    const float4* arow = (const float4*)(adj + (size_t)i * NN);
    const float4* xp4 = (const float4*)g_xp;

    float4 acc = make_float4(0.f, 0.f, 0.f, 0.f);
    float wsum = 0.f;

    const int jbase0 = warp * 1024;
    for (int it = 0; it < 8; ++it) {
        const int base = jbase0 + it * 128;
        const float4 v = __ldg(&arow[(base >> 2) + lane]);
        const float va[4] = {v.x, v.y, v.z, v.w};
#pragma unroll
        for (int e = 0; e < 4; ++e) {
            const int j = base + lane * 4 + e;
            const bool nz = (va[e] > 0.f) || (j == i);   // adj + I > 0
            unsigned ball = __ballot_sync(0xffffffffu, nz);
            while (ball) {
                const int b = __ffs(ball) - 1; ball &= ball - 1;
                const int jj = base + b * 4 + e;
                const float sd = __ldg(&g_sdst[jj]);     // broadcast, L2-hot
                float sv = si + sd; sv = sv > 0.f ? sv : NEG * sv;
                const float w = __expf(sv - mv);
                const float4 xv = __ldg(&xp4[jj * 32 + lane]);  // 512B/warp, L2
                acc.x += w * xv.x; acc.y += w * xv.y;
                acc.z += w * xv.z; acc.w += w * xv.w;
                wsum += w;
            }
        }
    }

    __shared__ float accsh[8][128];
    __shared__ float sumsh[8];
    *(float4*)&accsh[warp][lane * 4] = acc;
    if (lane == 0) sumsh[warp] = wsum;
    __syncthreads();

    if (threadIdx.x < 128) {
        const int f = threadIdx.x;
        float tot = 0.f, s = 0.f;
#pragma unroll
        for (int wv = 0; wv < 8; ++wv) { tot += accsh[wv][f]; s += sumsh[wv]; }
        out[(size_t)i * FF + f] = tot / s;
    }
}

// ---------------------------------------------------------------------------
extern "C" void kernel_launch(void* const* d_in, const int* in_sizes, int n_in,
                              void* d_out, int out_size) {
    const float* adj  = (const float*)d_in[0];
    const float* x    = (const float*)d_in[1];
    const float* w    = (const float*)d_in[2];
    const float* bias = (const float*)d_in[3];
    const float* phi  = (const float*)d_in[4];
    float* out = (float*)d_out;

    k_init <<<1, 1>>>();
    k_gemm <<<NN / 32, 256>>>(x, w, bias);
    k_score<<<NN / 8, 256>>>(phi);
    k_attn <<<NN, 256>>>(adj, out);
}

// round 4
// speedup vs baseline: 1.0340x; 1.0340x over previous
#include <cuda_runtime.h>
#include <cstdint>

#define NN 8192
#define FF 128
#define NEG 0.2f

// Scratch (no allocations allowed -> __device__ globals)
__device__ float g_xp[(size_t)NN * FF];   // x' = x@W + b  (4 MB, L2-resident)
__device__ float g_ssrc[NN];
__device__ float g_sdst[NN];
__device__ unsigned g_maxbits;            // ordered-encoded max of s_dst

__global__ void k_init() { g_maxbits = 0u; }

// ---------------------------------------------------------------------------
// K1: x' = x @ W + bias      (8192x128 @ 128x128 fp32)
// block = 256 threads, 32 rows per block; W half-tile (64x128) in shared.
// ---------------------------------------------------------------------------
__global__ void k_gemm(const float* __restrict__ x,
                       const float* __restrict__ w,
                       const float* __restrict__ bias) {
    __shared__ float ws[64][128];   // [kk][c]
    __shared__ float xs[32][64];    // [r][kk]
    const int tid = threadIdx.x;
    const int row0 = blockIdx.x * 32;
    const int c  = tid & 127;
    const int rr = tid >> 7;        // 0 or 1 -> rows rr*16 .. rr*16+15

    float acc[16];
#pragma unroll
    for (int q = 0; q < 16; ++q) acc[q] = 0.f;

    for (int kb = 0; kb < 128; kb += 64) {
        for (int t = tid; t < 64 * 128; t += 256)
            ws[t >> 7][t & 127] = w[(kb + (t >> 7)) * 128 + (t & 127)];
        for (int t = tid; t < 32 * 64; t += 256) {
            int r = t >> 6, kk = t & 63;
            xs[r][kk] = x[(size_t)(row0 + r) * 128 + kb + kk];
        }
        __syncthreads();
#pragma unroll 4
        for (int kk = 0; kk < 64; ++kk) {
            float wv = ws[kk][c];
#pragma unroll
            for (int q = 0; q < 16; ++q)
                acc[q] += xs[rr * 16 + q][kk] * wv;   // broadcast LDS
        }
        __syncthreads();
    }
    const float b = bias[c];
#pragma unroll
    for (int q = 0; q < 16; ++q)
        g_xp[(size_t)(row0 + rr * 16 + q) * 128 + c] = acc[q] + b;
}

// ---------------------------------------------------------------------------
// K2: s_src[i] = x'_i . phi[:F],  s_dst[i] = x'_i . phi[F:], global max(s_dst)
// warp per row.
// ---------------------------------------------------------------------------
__global__ void k_score(const float* __restrict__ phi) {
    const int warp = threadIdx.x >> 5, lane = threadIdx.x & 31;
    const int i = blockIdx.x * 8 + warp;
    const float4* xr = (const float4*)(g_xp + (size_t)i * FF);
    const float4* pl = (const float4*)phi;
    const float4* ph = (const float4*)(phi + FF);
    float4 xv = xr[lane], a = pl[lane], b = ph[lane];
    float s1 = xv.x * a.x + xv.y * a.y + xv.z * a.z + xv.w * a.w;
    float s2 = xv.x * b.x + xv.y * b.y + xv.z * b.z + xv.w * b.w;
#pragma unroll
    for (int o = 16; o; o >>= 1) {
        s1 += __shfl_xor_sync(0xffffffffu, s1, o);
        s2 += __shfl_xor_sync(0xffffffffu, s2, o);
    }
    if (lane == 0) {
        g_ssrc[i] = s1;
        g_sdst[i] = s2;
        unsigned bits = __float_as_uint(s2);
        unsigned enc = bits ^ ((bits >> 31) ? 0xFFFFFFFFu : 0x80000000u);
        atomicMax(&g_maxbits, enc);   // order-independent -> deterministic
    }
}

// ---------------------------------------------------------------------------
// K3: fused masked softmax + aggregation, one block (8 warps) per row i.
// Warp w scans j in [w*1024, w*1024+1024): coalesced float4 adj loads,
// ballot-enumerate nonzeros (fixed order -> deterministic), gather x'_j
// from L2 with weight exp(leaky(s_i+s_j) - m_i). Fixed-order warp combine.
// ---------------------------------------------------------------------------
__global__ void k_attn(const float* __restrict__ adj, float* __restrict__ out) {
    const int i = blockIdx.x;
    const int warp = threadIdx.x >> 5, lane = threadIdx.x & 31;

    const unsigned u = g_maxbits;
    const float dmax = __uint_as_float(u ^ ((u >> 31) ? 0x80000000u : 0xFFFFFFFFu));
    const float si = g_ssrc[i];
    float mv = si + dmax; mv = mv > 0.f ? mv : NEG * mv;   // >= all row scores

    const float4* arow = (const float4*)(adj + (size_t)i * NN);
    const float4* xp4 = (const float4*)g_xp;

    float4 acc = make_float4(0.f, 0.f, 0.f, 0.f);
    float wsum = 0.f;

    const int jbase0 = warp * 1024;
    for (int it = 0; it < 8; ++it) {
        const int base = jbase0 + it * 128;
        const float4 v = __ldg(&arow[(base >> 2) + lane]);
        const float va[4] = {v.x, v.y, v.z, v.w};
#pragma unroll
        for (int e = 0; e < 4; ++e) {
            const int j = base + lane * 4 + e;
            const bool nz = (va[e] > 0.f) || (j == i);   // adj + I > 0
            unsigned ball = __ballot_sync(0xffffffffu, nz);
            while (ball) {
                const int b = __ffs(ball) - 1; ball &= ball - 1;
                const int jj = base + b * 4 + e;
                const float sd = __ldg(&g_sdst[jj]);     // broadcast, L2-hot
                float sv = si + sd; sv = sv > 0.f ? sv : NEG * sv;
                const float w = __expf(sv - mv);
                const float4 xv = __ldg(&xp4[jj * 32 + lane]);  // 512B/warp, L2
                acc.x += w * xv.x; acc.y += w * xv.y;
                acc.z += w * xv.z; acc.w += w * xv.w;
                wsum += w;
            }
        }
    }

    __shared__ float accsh[8][128];
    __shared__ float sumsh[8];
    *(float4*)&accsh[warp][lane * 4] = acc;
    if (lane == 0) sumsh[warp] = wsum;
    __syncthreads();

    if (threadIdx.x < 128) {
        const int f = threadIdx.x;
        float tot = 0.f, s = 0.f;
#pragma unroll
        for (int wv = 0; wv < 8; ++wv) { tot += accsh[wv][f]; s += sumsh[wv]; }
        out[(size_t)i * FF + f] = tot / s;
    }
}

// ---------------------------------------------------------------------------
extern "C" void kernel_launch(void* const* d_in, const int* in_sizes, int n_in,
                              void* d_out, int out_size) {
    const float* adj  = (const float*)d_in[0];
    const float* x    = (const float*)d_in[1];
    const float* w    = (const float*)d_in[2];
    const float* bias = (const float*)d_in[3];
    const float* phi  = (const float*)d_in[4];
    float* out = (float*)d_out;

    k_init <<<1, 1>>>();
    k_gemm <<<NN / 32, 256>>>(x, w, bias);
    k_score<<<NN / 8, 256>>>(phi);
    k_attn <<<NN, 256>>>(adj, out);
}